// round 1
// baseline (speedup 1.0000x reference)
#include <cuda_runtime.h>

#define N_NODES 50000
#define N_EDGES 800000
#define IN_NODE 128
#define IN_EDGE 64
#define HID 64
#define INV_SQRT8 0.35355339059327373f

// ---------------- scratch (device globals; no allocation allowed) ----------
__device__ float g_Q[N_NODES * HID];
__device__ float g_K[N_NODES * HID];
__device__ float g_V[N_NODES * HID];
__device__ float g_wV[N_NODES * HID];
__device__ float g_z[N_NODES * 8];
__device__ float g_cnt[N_NODES];
__device__ int   g_is64;

// ---------------- f32x2 packed-FMA helpers (Blackwell: only via PTX) -------
static __device__ __forceinline__ unsigned long long pk2(float x, float y) {
    unsigned long long r;
    asm("mov.b64 %0,{%1,%2};" : "=l"(r) : "f"(x), "f"(y));
    return r;
}
static __device__ __forceinline__ void fma2(unsigned long long& d,
                                            unsigned long long a,
                                            unsigned long long b) {
    asm("fma.rn.f32x2 %0,%1,%2,%3;" : "=l"(d) : "l"(a), "l"(b), "l"(d));
}
static __device__ __forceinline__ float2 up2(unsigned long long v) {
    float2 f;
    asm("mov.b64 {%0,%1},%2;" : "=f"(f.x), "=f"(f.y) : "l"(v));
    return f;
}
static __device__ __forceinline__ void red_add_v2(float* p, float x, float y) {
    asm volatile("red.global.add.v2.f32 [%0],{%1,%2};" ::"l"(p), "f"(x), "f"(y)
                 : "memory");
}

// ------------- detect whether edge_index is int64 or int32 -----------------
__global__ void detect_kernel(const void* ei) {
    if (threadIdx.x == 0 && blockIdx.x == 0) {
        const long long* p = (const long long*)ei;
        int ok = 1;
        for (int i = 0; i < 16; i++) {
            long long v = p[i];
            if (v < 0 || v >= N_NODES) ok = 0;
        }
        g_is64 = ok;
    }
}

static __device__ __forceinline__ long long get_idx(const void* ei, long long i,
                                                    int is64) {
    if (is64) return ((const long long*)ei)[i];
    return (long long)((const int*)ei)[i];
}

// ------------- zero accumulators -------------------------------------------
__global__ void zero_kernel() {
    int i = blockIdx.x * blockDim.x + threadIdx.x;
    if (i < N_NODES * HID) g_wV[i] = 0.0f;
    if (i < N_NODES * 8) g_z[i] = 0.0f;
    if (i < N_NODES) g_cnt[i] = 0.0f;
}

// ------------- node projection: out = h @ W + b ----------------------------
// block = 128 threads (4 warps), each warp owns 4 nodes, each lane owns a
// column PAIR (2*lane, 2*lane+1) with f32x2 accumulators.
__global__ void __launch_bounds__(128) proj_kernel(const float* __restrict__ h,
                                                   const float* __restrict__ W,
                                                   const float* __restrict__ b,
                                                   int which) {
    __shared__ float Ws[IN_NODE * HID];   // 32 KB, [k][c]
    __shared__ float bs[HID];
    __shared__ float hs[4][4 * IN_NODE];  // 8 KB

    float* out = (which == 0) ? g_Q : (which == 1) ? g_K : g_V;

    int tid = threadIdx.x;
    {
        const float4* W4 = (const float4*)W;
        float4* Ws4 = (float4*)Ws;
        #pragma unroll
        for (int i = tid; i < IN_NODE * HID / 4; i += 128) Ws4[i] = W4[i];
        if (tid < HID) bs[tid] = b[tid];
    }
    __syncthreads();

    int warp = tid >> 5, lane = tid & 31;
    long long nbase = (long long)blockIdx.x * 16 + warp * 4;

    {   // stage 4 h-rows (512 floats = 128 float4) into smem
        const float4* s4 = (const float4*)(h + nbase * IN_NODE);
        float4* d4 = (float4*)hs[warp];
        d4[lane] = s4[lane];
        d4[lane + 32] = s4[lane + 32];
        d4[lane + 64] = s4[lane + 64];
        d4[lane + 96] = s4[lane + 96];
    }
    __syncwarp();

    unsigned long long acc0, acc1, acc2, acc3;
    {
        float2 b2 = *(const float2*)&bs[2 * lane];
        unsigned long long bb = pk2(b2.x, b2.y);
        acc0 = acc1 = acc2 = acc3 = bb;
    }

    const float* hw = hs[warp];
    #pragma unroll 4
    for (int k = 0; k < IN_NODE; k += 2) {
        float2 w0 = *(const float2*)&Ws[k * HID + 2 * lane];
        float2 w1 = *(const float2*)&Ws[(k + 1) * HID + 2 * lane];
        unsigned long long W0 = pk2(w0.x, w0.y);
        unsigned long long W1 = pk2(w1.x, w1.y);
        float2 e0 = *(const float2*)&hw[0 * IN_NODE + k];
        float2 e1 = *(const float2*)&hw[1 * IN_NODE + k];
        float2 e2 = *(const float2*)&hw[2 * IN_NODE + k];
        float2 e3 = *(const float2*)&hw[3 * IN_NODE + k];
        fma2(acc0, pk2(e0.x, e0.x), W0); fma2(acc0, pk2(e0.y, e0.y), W1);
        fma2(acc1, pk2(e1.x, e1.x), W0); fma2(acc1, pk2(e1.y, e1.y), W1);
        fma2(acc2, pk2(e2.x, e2.x), W0); fma2(acc2, pk2(e2.y, e2.y), W1);
        fma2(acc3, pk2(e3.x, e3.x), W0); fma2(acc3, pk2(e3.y, e3.y), W1);
    }

    float2 r0 = up2(acc0), r1 = up2(acc1), r2 = up2(acc2), r3 = up2(acc3);
    *(float2*)&out[(nbase + 0) * HID + 2 * lane] = r0;
    *(float2*)&out[(nbase + 1) * HID + 2 * lane] = r1;
    *(float2*)&out[(nbase + 2) * HID + 2 * lane] = r2;
    *(float2*)&out[(nbase + 3) * HID + 2 * lane] = r3;
}

// ------------- fused edge kernel -------------------------------------------
// pe = e @ We + be ; score = K[src]*Q[dst]/sqrt(8) + pe ; e_out = score
// a = exp(clip(per-head sum)) ; scatter wV/z/cnt by src.
// block = 256 threads (8 warps), 4 edges/warp, lane = column pair.
__global__ void __launch_bounds__(256) edge_kernel(const void* __restrict__ ei,
                                                   const float* __restrict__ e,
                                                   const float* __restrict__ We,
                                                   const float* __restrict__ be,
                                                   float* __restrict__ e_out) {
    __shared__ float Ws[IN_EDGE * HID];  // 16 KB
    __shared__ float bs[HID];
    __shared__ float es[8][4 * IN_EDGE]; // 8 KB

    int tid = threadIdx.x;
    {
        const float4* W4 = (const float4*)We;
        float4* Ws4 = (float4*)Ws;
        #pragma unroll
        for (int i = tid; i < IN_EDGE * HID / 4; i += 256) Ws4[i] = W4[i];
        if (tid < HID) bs[tid] = be[tid];
    }
    __syncthreads();

    int warp = tid >> 5, lane = tid & 31;
    int is64 = g_is64;
    const int n_tiles = N_EDGES / 32;
    float2 b2 = *(const float2*)&bs[2 * lane];
    unsigned long long bias = pk2(b2.x, b2.y);

    for (int tile = blockIdx.x; tile < n_tiles; tile += gridDim.x) {
        long long base = (long long)tile * 32 + warp * 4;

        {   // stage 4 e-rows (256 floats = 64 float4)
            const float4* s4 = (const float4*)(e + base * IN_EDGE);
            float4* d4 = (float4*)es[warp];
            d4[lane] = s4[lane];
            d4[lane + 32] = s4[lane + 32];
        }
        __syncwarp();

        unsigned long long acc0 = bias, acc1 = bias, acc2 = bias, acc3 = bias;
        const float* ew = es[warp];
        #pragma unroll 8
        for (int k = 0; k < IN_EDGE; k += 2) {
            float2 w0 = *(const float2*)&Ws[k * HID + 2 * lane];
            float2 w1 = *(const float2*)&Ws[(k + 1) * HID + 2 * lane];
            unsigned long long W0 = pk2(w0.x, w0.y);
            unsigned long long W1 = pk2(w1.x, w1.y);
            float2 e0 = *(const float2*)&ew[0 * IN_EDGE + k];
            float2 e1 = *(const float2*)&ew[1 * IN_EDGE + k];
            float2 e2 = *(const float2*)&ew[2 * IN_EDGE + k];
            float2 e3 = *(const float2*)&ew[3 * IN_EDGE + k];
            fma2(acc0, pk2(e0.x, e0.x), W0); fma2(acc0, pk2(e0.y, e0.y), W1);
            fma2(acc1, pk2(e1.x, e1.x), W0); fma2(acc1, pk2(e1.y, e1.y), W1);
            fma2(acc2, pk2(e2.x, e2.x), W0); fma2(acc2, pk2(e2.y, e2.y), W1);
            fma2(acc3, pk2(e3.x, e3.x), W0); fma2(acc3, pk2(e3.y, e3.y), W1);
        }
        __syncwarp();  // all lanes done reading es before next tile overwrite

        #pragma unroll
        for (int j = 0; j < 4; j++) {
            unsigned long long acc =
                (j == 0) ? acc0 : (j == 1) ? acc1 : (j == 2) ? acc2 : acc3;
            long long eidx = base + j;
            long long s = get_idx(ei, eidx, is64);
            long long d = get_idx(ei, (long long)N_EDGES + eidx, is64);

            float2 Ks = *(const float2*)&g_K[s * HID + 2 * lane];
            float2 Qd = *(const float2*)&g_Q[d * HID + 2 * lane];
            float2 Vs = *(const float2*)&g_V[s * HID + 2 * lane];
            float2 pe = up2(acc);
            float2 sc;
            sc.x = fmaf(Ks.x * Qd.x, INV_SQRT8, pe.x);
            sc.y = fmaf(Ks.y * Qd.y, INV_SQRT8, pe.y);

            *(float2*)&e_out[eidx * HID + 2 * lane] = sc;

            // per-head sum: head = lane/4 (8 cols per head = 4 lanes)
            float ssum = sc.x + sc.y;
            ssum += __shfl_xor_sync(0xffffffffu, ssum, 1);
            ssum += __shfl_xor_sync(0xffffffffu, ssum, 2);
            float a = __expf(fminf(fmaxf(ssum, -5.0f), 5.0f));

            red_add_v2(&g_wV[s * HID + 2 * lane], Vs.x * a, Vs.y * a);
            if ((lane & 3) == 0)
                atomicAdd(&g_z[s * 8 + (lane >> 2)], a);
            if (lane == 0) atomicAdd(&g_cnt[s], 1.0f);
        }
    }
}

// ------------- final combine: h_out = wV / (z_sum/max(cnt,1) + 1e-6) -------
__global__ void final_kernel(float* __restrict__ h_out) {
    int i = blockIdx.x * blockDim.x + threadIdx.x;
    if (i >= N_NODES * HID) return;
    int n = i >> 6;
    int c = i & 63;
    float cnt = g_cnt[n];
    float z = g_z[n * 8 + (c >> 3)] / fmaxf(cnt, 1.0f);
    h_out[i] = g_wV[i] / (z + 1e-6f);
}

// ---------------------------------------------------------------------------
extern "C" void kernel_launch(void* const* d_in, const int* in_sizes, int n_in,
                              void* d_out, int out_size) {
    const void* ei = d_in[0];
    const float* h = (const float*)d_in[1];
    const float* e = (const float*)d_in[2];
    const float* WQ = (const float*)d_in[3];
    const float* bQ = (const float*)d_in[4];
    const float* WK = (const float*)d_in[5];
    const float* bK = (const float*)d_in[6];
    const float* WV = (const float*)d_in[7];
    const float* bV = (const float*)d_in[8];
    const float* We = (const float*)d_in[9];
    const float* be = (const float*)d_in[10];

    float* out = (float*)d_out;
    float* h_out = out;                                  // [50000*64]
    float* e_out = out + (long long)N_NODES * HID;       // [800000*64]

    detect_kernel<<<1, 32>>>(ei);
    zero_kernel<<<(N_NODES * HID + 1023) / 1024, 1024>>>();
    proj_kernel<<<N_NODES / 16, 128>>>(h, WQ, bQ, 0);
    proj_kernel<<<N_NODES / 16, 128>>>(h, WK, bK, 1);
    proj_kernel<<<N_NODES / 16, 128>>>(h, WV, bV, 2);
    edge_kernel<<<2048, 256>>>(ei, e, We, be, e_out);
    final_kernel<<<(N_NODES * HID + 255) / 256, 256>>>(h_out);
}

// round 2
// speedup vs baseline: 1.0706x; 1.0706x over previous
#include <cuda_runtime.h>

#define N_NODES 50000
#define N_EDGES 800000
#define IN_NODE 128
#define HID 64
#define INV_SQRT8 0.35355339059327373f

typedef unsigned long long ull;

// ---------------- scratch (device globals; no allocation allowed) ----------
__device__ float g_Q[N_NODES * HID];
__device__ float g_K[N_NODES * HID];
__device__ float g_V[N_NODES * HID];
__device__ float g_wV[N_NODES * HID];
__device__ float g_z[N_NODES * 8];
__device__ float g_cnt[N_NODES];
__device__ int   g_is64;

// ---------------- f32x2 packed-FMA helpers (Blackwell: only via PTX) -------
static __device__ __forceinline__ void fma2(ull& d, ull a, ull b) {
    asm("fma.rn.f32x2 %0,%1,%2,%3;" : "=l"(d) : "l"(a), "l"(b), "l"(d));
}
static __device__ __forceinline__ float2 up2(ull v) {
    float2 f;
    asm("mov.b64 {%0,%1},%2;" : "=f"(f.x), "=f"(f.y) : "l"(v));
    return f;
}
static __device__ __forceinline__ void red_add_v4(float* p, float x, float y,
                                                  float z, float w) {
    asm volatile("red.global.add.v4.f32 [%0],{%1,%2,%3,%4};" ::"l"(p), "f"(x),
                 "f"(y), "f"(z), "f"(w)
                 : "memory");
}

static __device__ __forceinline__ long long get_idx(const void* ei, long long i,
                                                    int is64) {
    if (is64) return ((const long long*)ei)[i];
    return (long long)((const int*)ei)[i];
}

// ------------- zero accumulators + int64/int32 sniff -----------------------
__global__ void zero_detect_kernel(const void* ei) {
    long long i = (long long)blockIdx.x * blockDim.x + threadIdx.x;
    if (i == 0) {
        const long long* p = (const long long*)ei;
        int ok = 1;
        for (int t = 0; t < 16; t++) {
            long long v = p[t];
            if (v < 0 || v >= N_NODES) ok = 0;
        }
        g_is64 = ok;
    }
    float4 z4 = make_float4(0.f, 0.f, 0.f, 0.f);
    if (i < N_NODES * HID / 4) ((float4*)g_wV)[i] = z4;
    if (i < N_NODES * 2) ((float4*)g_z)[i] = z4;
    if (i < N_NODES / 4) ((float4*)g_cnt)[i] = z4;
}

// ------------- fused node projections: Q,K,V = h @ W* + b* -----------------
// block = 512 threads (16 warps), warp owns 4 nodes, lane owns a column pair.
// h rows staged DUPLICATED ({v,v}) so broadcast operands are direct LDS.64.
__global__ void __launch_bounds__(512)
proj_fused_kernel(const float* __restrict__ h, const float* __restrict__ WQ,
                  const float* __restrict__ bQ, const float* __restrict__ WK,
                  const float* __restrict__ bK, const float* __restrict__ WV,
                  const float* __restrict__ bV) {
    extern __shared__ float sm[];
    float* Wq = sm;               // 8192 floats
    float* Wk = sm + 8192;        // 8192
    float* Wv = sm + 16384;       // 8192
    float* hsd = sm + 24576;      // 16 warps * 1024 floats (4 rows * 128k * 2)

    int tid = threadIdx.x;
    #pragma unroll
    for (int i = tid; i < 2048; i += 512) {
        ((float4*)Wq)[i] = ((const float4*)WQ)[i];
        ((float4*)Wk)[i] = ((const float4*)WK)[i];
        ((float4*)Wv)[i] = ((const float4*)WV)[i];
    }
    __syncthreads();

    int warp = tid >> 5, lane = tid & 31;
    long long nbase = ((long long)blockIdx.x * 16 + warp) * 4;
    if (nbase >= N_NODES) return;

    float* hw = hsd + warp * 1024;
    {   // stage 4 h-rows duplicated
        const float4* s4 = (const float4*)(h + nbase * IN_NODE);
        #pragma unroll
        for (int u = 0; u < 4; u++) {
            int i = lane + u * 32;            // [0,128): row=i>>5, kq=(i&31)*4
            float4 v = s4[i];
            float* dst = hw + (i >> 5) * 256 + ((i & 31) << 3);
            *(float4*)(dst) = make_float4(v.x, v.x, v.y, v.y);
            *(float4*)(dst + 4) = make_float4(v.z, v.z, v.w, v.w);
        }
    }
    __syncwarp();

    int co = 2 * lane;
    ull aq[4], ak[4], av[4];
    {
        ull bq = *(const ull*)&bQ[co];
        ull bk = *(const ull*)&bK[co];
        ull bv = *(const ull*)&bV[co];
        #pragma unroll
        for (int j = 0; j < 4; j++) { aq[j] = bq; ak[j] = bk; av[j] = bv; }
    }

    #pragma unroll 4
    for (int k = 0; k < IN_NODE; k++) {
        ull wq = *(const ull*)&Wq[k * HID + co];
        ull wk = *(const ull*)&Wk[k * HID + co];
        ull wv = *(const ull*)&Wv[k * HID + co];
        #pragma unroll
        for (int j = 0; j < 4; j++) {
            ull ev = *(const ull*)&hw[j * 256 + 2 * k];
            fma2(aq[j], ev, wq);
            fma2(ak[j], ev, wk);
            fma2(av[j], ev, wv);
        }
    }

    #pragma unroll
    for (int j = 0; j < 4; j++) {
        long long o = (nbase + j) * HID + co;
        *(float2*)&g_Q[o] = up2(aq[j]);
        *(float2*)&g_K[o] = up2(ak[j]);
        *(float2*)&g_V[o] = up2(av[j]);
    }
}

// ------------- fused edge kernel -------------------------------------------
// layout: 2 edges per warp-row (half = lane>>4), lane owns 4 columns.
// 8 edges per warp per tile; 8 warps -> 64 edges per block-tile; 12500 tiles.
__global__ void __launch_bounds__(256)
edge_kernel(const void* __restrict__ ei, const float* __restrict__ e,
            const float* __restrict__ We, const float* __restrict__ be,
            float* __restrict__ e_out) {
    extern __shared__ float sm[];
    float* Ws = sm;              // 4096 floats
    float* esd = sm + 4096;      // 8 warps * 1024 floats (8 rows * 64k * 2)

    int tid = threadIdx.x;
    #pragma unroll
    for (int i = tid; i < 1024; i += 256)
        ((float4*)Ws)[i] = ((const float4*)We)[i];
    __syncthreads();

    int warp = tid >> 5, lane = tid & 31;
    int cg = lane & 15, half = lane >> 4;
    int is64 = g_is64;
    float* ew = esd + warp * 1024;
    const float* wp = Ws + 4 * cg;
    ull bias0 = *(const ull*)&be[4 * cg];
    ull bias1 = *(const ull*)&be[4 * cg + 2];

    for (int t = blockIdx.x; t < 12500; t += gridDim.x) {
        long long base = (long long)t * 64 + warp * 8;

        {   // stage 8 e-rows duplicated
            const float4* s4 = (const float4*)(e + base * HID);
            #pragma unroll
            for (int u = 0; u < 4; u++) {
                int i = lane + u * 32;        // [0,128): row=i>>4, kq=(i&15)*4
                float4 v = s4[i];
                float* dst = ew + (i >> 4) * 128 + ((i & 15) << 3);
                *(float4*)(dst) = make_float4(v.x, v.x, v.y, v.y);
                *(float4*)(dst + 4) = make_float4(v.z, v.z, v.w, v.w);
            }
        }

        long long sidx[4], didx[4];
        #pragma unroll
        for (int j = 0; j < 4; j++) {
            long long eidx = base + 2 * j + half;
            sidx[j] = get_idx(ei, eidx, is64);
            didx[j] = get_idx(ei, (long long)N_EDGES + eidx, is64);
        }
        __syncwarp();

        ull acc0[4], acc1[4];
        #pragma unroll
        for (int j = 0; j < 4; j++) { acc0[j] = bias0; acc1[j] = bias1; }

        #pragma unroll 4
        for (int k = 0; k < HID; k++) {
            ull w0 = *(const ull*)&wp[k * HID];
            ull w1 = *(const ull*)&wp[k * HID + 2];
            #pragma unroll
            for (int j = 0; j < 4; j++) {
                ull ev = *(const ull*)&ew[(2 * j + half) * 128 + 2 * k];
                fma2(acc0[j], ev, w0);
                fma2(acc1[j], ev, w1);
            }
        }
        __syncwarp();

        #pragma unroll
        for (int j = 0; j < 4; j++) {
            long long eidx = base + 2 * j + half;
            long long s = sidx[j], d = didx[j];
            float4 Ks = *(const float4*)&g_K[s * HID + 4 * cg];
            float4 Qd = *(const float4*)&g_Q[d * HID + 4 * cg];
            float4 Vs = *(const float4*)&g_V[s * HID + 4 * cg];
            float2 p0 = up2(acc0[j]), p1 = up2(acc1[j]);
            float4 sc;
            sc.x = fmaf(Ks.x * Qd.x, INV_SQRT8, p0.x);
            sc.y = fmaf(Ks.y * Qd.y, INV_SQRT8, p0.y);
            sc.z = fmaf(Ks.z * Qd.z, INV_SQRT8, p1.x);
            sc.w = fmaf(Ks.w * Qd.w, INV_SQRT8, p1.y);
            *(float4*)&e_out[eidx * HID + 4 * cg] = sc;

            float ss = sc.x + sc.y + sc.z + sc.w;   // head = cg>>1
            ss += __shfl_xor_sync(0xffffffffu, ss, 1);
            float a = __expf(fminf(fmaxf(ss, -5.0f), 5.0f));

            red_add_v4(&g_wV[s * HID + 4 * cg], Vs.x * a, Vs.y * a, Vs.z * a,
                       Vs.w * a);
            if (!(cg & 1)) atomicAdd(&g_z[s * 8 + (cg >> 1)], a);
            if (cg == 0) atomicAdd(&g_cnt[s], 1.0f);
        }
    }
}

// ------------- final combine: h_out = wV / (z_sum/max(cnt,1) + 1e-6) -------
__global__ void final_kernel(float* __restrict__ h_out) {
    int i = blockIdx.x * blockDim.x + threadIdx.x;   // float4 index
    if (i >= N_NODES * HID / 4) return;
    int n = i >> 4;
    int cg = i & 15;
    float cnt = g_cnt[n];
    float z = g_z[n * 8 + (cg >> 1)] / fmaxf(cnt, 1.0f);
    float inv = 1.0f / (z + 1e-6f);
    float4 w = ((const float4*)g_wV)[i];
    w.x *= inv; w.y *= inv; w.z *= inv; w.w *= inv;
    ((float4*)h_out)[i] = w;
}

// ---------------------------------------------------------------------------
extern "C" void kernel_launch(void* const* d_in, const int* in_sizes, int n_in,
                              void* d_out, int out_size) {
    const void* ei = d_in[0];
    const float* h = (const float*)d_in[1];
    const float* e = (const float*)d_in[2];
    const float* WQ = (const float*)d_in[3];
    const float* bQ = (const float*)d_in[4];
    const float* WK = (const float*)d_in[5];
    const float* bK = (const float*)d_in[6];
    const float* WV = (const float*)d_in[7];
    const float* bV = (const float*)d_in[8];
    const float* We = (const float*)d_in[9];
    const float* be = (const float*)d_in[10];

    float* out = (float*)d_out;
    float* h_out = out;                             // [50000*64]
    float* e_out = out + (long long)N_NODES * HID;  // [800000*64]

    static int attr_done = 0;
    const int PROJ_SMEM = (24576 + 16 * 1024) * 4;  // 163840 B
    const int EDGE_SMEM = (4096 + 8 * 1024) * 4;    // 49152 B
    if (!attr_done) {
        cudaFuncSetAttribute(proj_fused_kernel,
                             cudaFuncAttributeMaxDynamicSharedMemorySize,
                             PROJ_SMEM);
        cudaFuncSetAttribute(edge_kernel,
                             cudaFuncAttributeMaxDynamicSharedMemorySize,
                             EDGE_SMEM);
        attr_done = 1;
    }

    zero_detect_kernel<<<3125, 256>>>(ei);
    proj_fused_kernel<<<782, 512, PROJ_SMEM>>>(h, WQ, bQ, WK, bK, WV, bV);
    edge_kernel<<<444, 256, EDGE_SMEM>>>(ei, e, We, be, e_out);
    final_kernel<<<(N_NODES * HID / 4 + 255) / 256, 256>>>(h_out);
}

// round 3
// speedup vs baseline: 1.0831x; 1.0117x over previous
#include <cuda_runtime.h>

#define N_NODES 50000
#define N_EDGES 800000
#define IN_NODE 128
#define HID 64
#define INV_SQRT8 0.35355339059327373f

typedef unsigned long long ull;

// ---------------- scratch (device globals; no allocation allowed) ----------
__device__ float g_Q[N_NODES * HID];
__device__ float g_K[N_NODES * HID];
__device__ float g_V[N_NODES * HID];
__device__ float g_z[N_NODES * 8];     // per-node per-head sum of a
__device__ float g_cnt[N_NODES];
__device__ int   g_is64;

// ---------------- f32x2 packed-FMA helpers (Blackwell: only via PTX) -------
static __device__ __forceinline__ void fma2(ull& d, ull a, ull b) {
    asm("fma.rn.f32x2 %0,%1,%2,%3;" : "=l"(d) : "l"(a), "l"(b), "l"(d));
}
static __device__ __forceinline__ float2 up2(ull v) {
    float2 f;
    asm("mov.b64 {%0,%1},%2;" : "=f"(f.x), "=f"(f.y) : "l"(v));
    return f;
}
static __device__ __forceinline__ void red_add_v2(float* p, float x, float y) {
    asm volatile("red.global.add.v2.f32 [%0],{%1,%2};" ::"l"(p), "f"(x), "f"(y)
                 : "memory");
}
static __device__ __forceinline__ void red_add_f32(float* p, float x) {
    asm volatile("red.global.add.f32 [%0],%1;" ::"l"(p), "f"(x) : "memory");
}

static __device__ __forceinline__ long long get_idx(const void* ei, long long i,
                                                    int is64) {
    if (is64) return ((const long long*)ei)[i];
    return (long long)((const int*)ei)[i];
}

// ------------- zero accumulators + int64/int32 sniff -----------------------
__global__ void zero_detect_kernel(const void* ei) {
    int i = blockIdx.x * blockDim.x + threadIdx.x;
    if (i == 0) {
        const long long* p = (const long long*)ei;
        int ok = 1;
        for (int t = 0; t < 16; t++) {
            long long v = p[t];
            if (v < 0 || v >= N_NODES) ok = 0;
        }
        g_is64 = ok;
    }
    float4 z4 = make_float4(0.f, 0.f, 0.f, 0.f);
    if (i < N_NODES * 2) ((float4*)g_z)[i] = z4;        // 100000 float4
    if (i < N_NODES / 4) ((float4*)g_cnt)[i] = z4;      // 12500 float4
}

// ------------- fused node projections: Q,K,V = h @ W* + b* -----------------
// block = 512 threads (16 warps), warp owns 4 nodes, lane owns a column pair.
// h rows staged DUPLICATED ({v,v}) so broadcast operands are direct LDS.64.
__global__ void __launch_bounds__(512)
proj_fused_kernel(const float* __restrict__ h, const float* __restrict__ WQ,
                  const float* __restrict__ bQ, const float* __restrict__ WK,
                  const float* __restrict__ bK, const float* __restrict__ WV,
                  const float* __restrict__ bV) {
    extern __shared__ float sm[];
    float* Wq = sm;               // 8192 floats
    float* Wk = sm + 8192;        // 8192
    float* Wv = sm + 16384;       // 8192
    float* hsd = sm + 24576;      // 16 warps * 1024 floats (4 rows * 128k * 2)

    int tid = threadIdx.x;
    #pragma unroll
    for (int i = tid; i < 2048; i += 512) {
        ((float4*)Wq)[i] = ((const float4*)WQ)[i];
        ((float4*)Wk)[i] = ((const float4*)WK)[i];
        ((float4*)Wv)[i] = ((const float4*)WV)[i];
    }
    __syncthreads();

    int warp = tid >> 5, lane = tid & 31;
    long long nbase = ((long long)blockIdx.x * 16 + warp) * 4;
    if (nbase >= N_NODES) return;

    float* hw = hsd + warp * 1024;
    {   // stage 4 h-rows duplicated
        const float4* s4 = (const float4*)(h + nbase * IN_NODE);
        #pragma unroll
        for (int u = 0; u < 4; u++) {
            int i = lane + u * 32;            // [0,128): row=i>>5, kq=(i&31)*4
            float4 v = s4[i];
            float* dst = hw + (i >> 5) * 256 + ((i & 31) << 3);
            *(float4*)(dst) = make_float4(v.x, v.x, v.y, v.y);
            *(float4*)(dst + 4) = make_float4(v.z, v.z, v.w, v.w);
        }
    }
    __syncwarp();

    int co = 2 * lane;
    ull aq[4], ak[4], av[4];
    {
        ull bq = *(const ull*)&bQ[co];
        ull bk = *(const ull*)&bK[co];
        ull bv = *(const ull*)&bV[co];
        #pragma unroll
        for (int j = 0; j < 4; j++) { aq[j] = bq; ak[j] = bk; av[j] = bv; }
    }

    #pragma unroll 4
    for (int k = 0; k < IN_NODE; k++) {
        ull wq = *(const ull*)&Wq[k * HID + co];
        ull wk = *(const ull*)&Wk[k * HID + co];
        ull wv = *(const ull*)&Wv[k * HID + co];
        #pragma unroll
        for (int j = 0; j < 4; j++) {
            ull ev = *(const ull*)&hw[j * 256 + 2 * k];
            fma2(aq[j], ev, wq);
            fma2(ak[j], ev, wk);
            fma2(av[j], ev, wv);
        }
    }

    #pragma unroll
    for (int j = 0; j < 4; j++) {
        long long o = (nbase + j) * HID + co;
        *(float2*)&g_Q[o] = up2(aq[j]);
        *(float2*)&g_K[o] = up2(ak[j]);
        *(float2*)&g_V[o] = up2(av[j]);
    }
}

// ------------- fused edge kernel -------------------------------------------
// pe = e @ We + be ; sc = K[src]*Q[dst]/sqrt(8) + pe ; e_out = sc
// a = exp(clip(per-head sum)); scatter ONLY per-head scalar a + count by src
// (wV scatter eliminated: wV[n] = V[n] * sum_a  — algebraic identity).
// layout: 2 edges per warp-row (half = lane>>4), lane owns 4 columns.
__global__ void __launch_bounds__(256)
edge_kernel(const void* __restrict__ ei, const float* __restrict__ e,
            const float* __restrict__ We, const float* __restrict__ be,
            float* __restrict__ e_out) {
    extern __shared__ float sm[];
    float* Ws = sm;              // 4096 floats
    float* esd = sm + 4096;      // 8 warps * 1024 floats (8 rows * 64k * 2)

    int tid = threadIdx.x;
    #pragma unroll
    for (int i = tid; i < 1024; i += 256)
        ((float4*)Ws)[i] = ((const float4*)We)[i];
    __syncthreads();

    int warp = tid >> 5, lane = tid & 31;
    int cg = lane & 15, half = lane >> 4;
    int is64 = g_is64;
    float* ew = esd + warp * 1024;
    const float* wp = Ws + 4 * cg;
    ull bias0 = *(const ull*)&be[4 * cg];
    ull bias1 = *(const ull*)&be[4 * cg + 2];

    for (int t = blockIdx.x; t < 12500; t += gridDim.x) {
        long long base = (long long)t * 64 + warp * 8;

        {   // stage 8 e-rows duplicated
            const float4* s4 = (const float4*)(e + base * HID);
            #pragma unroll
            for (int u = 0; u < 4; u++) {
                int i = lane + u * 32;        // [0,128): row=i>>4, kq=(i&15)*4
                float4 v = s4[i];
                float* dst = ew + (i >> 4) * 128 + ((i & 15) << 3);
                *(float4*)(dst) = make_float4(v.x, v.x, v.y, v.y);
                *(float4*)(dst + 4) = make_float4(v.z, v.z, v.w, v.w);
            }
        }

        long long sidx[4], didx[4];
        #pragma unroll
        for (int j = 0; j < 4; j++) {
            long long eidx = base + 2 * j + half;
            sidx[j] = get_idx(ei, eidx, is64);
            didx[j] = get_idx(ei, (long long)N_EDGES + eidx, is64);
        }
        __syncwarp();

        ull acc0[4], acc1[4];
        #pragma unroll
        for (int j = 0; j < 4; j++) { acc0[j] = bias0; acc1[j] = bias1; }

        #pragma unroll 4
        for (int k = 0; k < HID; k++) {
            ull w0 = *(const ull*)&wp[k * HID];
            ull w1 = *(const ull*)&wp[k * HID + 2];
            #pragma unroll
            for (int j = 0; j < 4; j++) {
                ull ev = *(const ull*)&ew[(2 * j + half) * 128 + 2 * k];
                fma2(acc0[j], ev, w0);
                fma2(acc1[j], ev, w1);
            }
        }
        __syncwarp();

        #pragma unroll
        for (int j = 0; j < 4; j++) {
            long long eidx = base + 2 * j + half;
            long long s = sidx[j], d = didx[j];
            float4 Ks = *(const float4*)&g_K[s * HID + 4 * cg];
            float4 Qd = *(const float4*)&g_Q[d * HID + 4 * cg];
            float2 p0 = up2(acc0[j]), p1 = up2(acc1[j]);
            float4 sc;
            sc.x = fmaf(Ks.x * Qd.x, INV_SQRT8, p0.x);
            sc.y = fmaf(Ks.y * Qd.y, INV_SQRT8, p0.y);
            sc.z = fmaf(Ks.z * Qd.z, INV_SQRT8, p1.x);
            sc.w = fmaf(Ks.w * Qd.w, INV_SQRT8, p1.y);
            *(float4*)&e_out[eidx * HID + 4 * cg] = sc;

            // per-head sum: head = cg>>1 (8 cols per head = 2 lanes)
            float ss = sc.x + sc.y + sc.z + sc.w;
            ss += __shfl_xor_sync(0xffffffffu, ss, 1);
            float a = __expf(fminf(fmaxf(ss, -5.0f), 5.0f));

            float a2 = __shfl_xor_sync(0xffffffffu, a, 2);  // head+1's a
            if ((cg & 3) == 0)
                red_add_v2(&g_z[s * 8 + (cg >> 1)], a, a2);
            if (cg == 0) red_add_f32(&g_cnt[s], 1.0f);
        }
    }
}

// ------------- final: h_out[n,h,:] = V[n,h,:]*S_h/(S_h/max(cnt,1)+1e-6) ----
__global__ void final_kernel(float* __restrict__ h_out) {
    int i = blockIdx.x * blockDim.x + threadIdx.x;   // float4 index
    if (i >= N_NODES * HID / 4) return;
    int n = i >> 4;
    int cg = i & 15;
    float S = g_z[n * 8 + (cg >> 1)];
    float cnt = g_cnt[n];
    float f = S / (S / fmaxf(cnt, 1.0f) + 1e-6f);
    float4 v = ((const float4*)g_V)[i];
    v.x *= f; v.y *= f; v.z *= f; v.w *= f;
    ((float4*)h_out)[i] = v;
}

// ---------------------------------------------------------------------------
extern "C" void kernel_launch(void* const* d_in, const int* in_sizes, int n_in,
                              void* d_out, int out_size) {
    const void* ei = d_in[0];
    const float* h = (const float*)d_in[1];
    const float* e = (const float*)d_in[2];
    const float* WQ = (const float*)d_in[3];
    const float* bQ = (const float*)d_in[4];
    const float* WK = (const float*)d_in[5];
    const float* bK = (const float*)d_in[6];
    const float* WV = (const float*)d_in[7];
    const float* bV = (const float*)d_in[8];
    const float* We = (const float*)d_in[9];
    const float* be = (const float*)d_in[10];

    float* out = (float*)d_out;
    float* h_out = out;                             // [50000*64]
    float* e_out = out + (long long)N_NODES * HID;  // [800000*64]

    static int attr_done = 0;
    const int PROJ_SMEM = (24576 + 16 * 1024) * 4;  // 163840 B
    const int EDGE_SMEM = (4096 + 8 * 1024) * 4;    // 49152 B
    if (!attr_done) {
        cudaFuncSetAttribute(proj_fused_kernel,
                             cudaFuncAttributeMaxDynamicSharedMemorySize,
                             PROJ_SMEM);
        cudaFuncSetAttribute(edge_kernel,
                             cudaFuncAttributeMaxDynamicSharedMemorySize,
                             EDGE_SMEM);
        attr_done = 1;
    }

    zero_detect_kernel<<<391, 256>>>(ei);
    proj_fused_kernel<<<782, 512, PROJ_SMEM>>>(h, WQ, bQ, WK, bK, WV, bV);
    edge_kernel<<<444, 256, EDGE_SMEM>>>(ei, e, We, be, e_out);
    final_kernel<<<(N_NODES * HID / 4 + 255) / 256, 256>>>(h_out);
}

// round 8
// speedup vs baseline: 1.1483x; 1.0602x over previous
#include <cuda_runtime.h>

#define N_NODES 50000
#define N_EDGES 800000
#define IN_NODE 128
#define HID 64
#define INV_SQRT8 0.35355339059327373f

typedef unsigned long long ull;

// ---------------- scratch (device globals; no allocation allowed) ----------
__device__ float g_Q[N_NODES * HID];
__device__ float g_K[N_NODES * HID];
__device__ float g_V[N_NODES * HID];
__device__ float g_z[N_NODES * 8];     // per-node per-head sum of a
__device__ float g_cnt[N_NODES];
__device__ int   g_is64;

// ---------------- f32x2 packed-FMA helpers (Blackwell: only via PTX) -------
static __device__ __forceinline__ void fma2(ull& d, ull a, ull b) {
    asm("fma.rn.f32x2 %0,%1,%2,%3;" : "=l"(d) : "l"(a), "l"(b), "l"(d));
}
static __device__ __forceinline__ float2 up2(ull v) {
    float2 f;
    asm("mov.b64 {%0,%1},%2;" : "=f"(f.x), "=f"(f.y) : "l"(v));
    return f;
}
static __device__ __forceinline__ ull dup2(float x) {
    ull r;
    asm("mov.b64 %0,{%1,%1};" : "=l"(r) : "f"(x));
    return r;
}
static __device__ __forceinline__ void red_add_v2(float* p, float x, float y) {
    asm volatile("red.global.add.v2.f32 [%0],{%1,%2};" ::"l"(p), "f"(x), "f"(y)
                 : "memory");
}
static __device__ __forceinline__ void red_add_f32(float* p, float x) {
    asm volatile("red.global.add.f32 [%0],%1;" ::"l"(p), "f"(x) : "memory");
}

static __device__ __forceinline__ long long get_idx(const void* ei, long long i,
                                                    int is64) {
    if (is64) return ((const long long*)ei)[i];
    return (long long)((const int*)ei)[i];
}

// ------------- zero accumulators + int64/int32 sniff -----------------------
__global__ void zero_detect_kernel(const void* ei) {
    int i = blockIdx.x * blockDim.x + threadIdx.x;
    if (i == 0) {
        const long long* p = (const long long*)ei;
        int ok = 1;
        for (int t = 0; t < 16; t++) {
            long long v = p[t];
            if (v < 0 || v >= N_NODES) ok = 0;
        }
        g_is64 = ok;
    }
    float4 z4 = make_float4(0.f, 0.f, 0.f, 0.f);
    if (i < N_NODES * 2) ((float4*)g_z)[i] = z4;
    if (i < N_NODES / 4) ((float4*)g_cnt)[i] = z4;
}

// ------------- fused node projections: Q,K,V = h @ W* + b* -----------------
__global__ void __launch_bounds__(512)
proj_fused_kernel(const float* __restrict__ h, const float* __restrict__ WQ,
                  const float* __restrict__ bQ, const float* __restrict__ WK,
                  const float* __restrict__ bK, const float* __restrict__ WV,
                  const float* __restrict__ bV) {
    extern __shared__ float sm[];
    float* Wq = sm;               // 8192 floats
    float* Wk = sm + 8192;        // 8192
    float* Wv = sm + 16384;       // 8192
    float* hsd = sm + 24576;      // 16 warps * 1024 floats (4 rows * 128k * 2)

    int tid = threadIdx.x;
    #pragma unroll
    for (int i = tid; i < 2048; i += 512) {
        ((float4*)Wq)[i] = ((const float4*)WQ)[i];
        ((float4*)Wk)[i] = ((const float4*)WK)[i];
        ((float4*)Wv)[i] = ((const float4*)WV)[i];
    }
    __syncthreads();

    int warp = tid >> 5, lane = tid & 31;
    long long nbase = ((long long)blockIdx.x * 16 + warp) * 4;
    if (nbase >= N_NODES) return;

    float* hw = hsd + warp * 1024;
    {   // stage 4 h-rows duplicated
        const float4* s4 = (const float4*)(h + nbase * IN_NODE);
        #pragma unroll
        for (int u = 0; u < 4; u++) {
            int i = lane + u * 32;
            float4 v = s4[i];
            float* dst = hw + (i >> 5) * 256 + ((i & 31) << 3);
            *(float4*)(dst) = make_float4(v.x, v.x, v.y, v.y);
            *(float4*)(dst + 4) = make_float4(v.z, v.z, v.w, v.w);
        }
    }
    __syncwarp();

    int co = 2 * lane;
    ull aq[4], ak[4], av[4];
    {
        ull bq = *(const ull*)&bQ[co];
        ull bk = *(const ull*)&bK[co];
        ull bv = *(const ull*)&bV[co];
        #pragma unroll
        for (int j = 0; j < 4; j++) { aq[j] = bq; ak[j] = bk; av[j] = bv; }
    }

    #pragma unroll 4
    for (int k = 0; k < IN_NODE; k++) {
        ull wq = *(const ull*)&Wq[k * HID + co];
        ull wk = *(const ull*)&Wk[k * HID + co];
        ull wv = *(const ull*)&Wv[k * HID + co];
        #pragma unroll
        for (int j = 0; j < 4; j++) {
            ull ev = *(const ull*)&hw[j * 256 + 2 * k];
            fma2(aq[j], ev, wq);
            fma2(ak[j], ev, wk);
            fma2(av[j], ev, wv);
        }
    }

    #pragma unroll
    for (int j = 0; j < 4; j++) {
        long long o = (nbase + j) * HID + co;
        *(float2*)&g_Q[o] = up2(aq[j]);
        *(float2*)&g_K[o] = up2(ak[j]);
        *(float2*)&g_V[o] = up2(av[j]);
    }
}

// ------------- fused edge kernel (edge-pair f32x2 packing) -----------------
// Warp processes 16 edges (8 pairs). Lane owns cols {2l, 2l+1}.
// es staged TRANSPOSED: es[k*16 + r] = e[base+r][k] -> one broadcast LDS.128
// yields two {e_E0[k], e_E1[k]} packs. W un-duplicated; {w,w} built with MOVs.
__global__ void __launch_bounds__(256)
edge_kernel(const void* __restrict__ ei, const float* __restrict__ e,
            const float* __restrict__ We, const float* __restrict__ be,
            float* __restrict__ e_out) {
    extern __shared__ float sm[];
    float* Ws = sm;                 // 4096 floats (64k x 64c)
    float* esd = sm + 4096;         // 8 warps * 1024 floats (64k x 16 edges)
    int* sidx = (int*)(sm + 12288); // 8 warps * 32 ints

    int tid = threadIdx.x;
    #pragma unroll
    for (int i = tid; i < 1024; i += 256)
        ((float4*)Ws)[i] = ((const float4*)We)[i];
    __syncthreads();

    int warp = tid >> 5, lane = tid & 31;
    int is64 = g_is64;
    float* ew = esd + warp * 1024;
    int* si = sidx + warp * 32;

    float2 b2 = *(const float2*)&be[2 * lane];
    ull bias0 = dup2(b2.x);
    ull bias1 = dup2(b2.y);

    for (int t = blockIdx.x; t < N_EDGES / 128; t += gridDim.x) {
        long long base = (long long)t * 128 + warp * 16;

        // stage indices: lanes 0-15 -> src, 16-31 -> dst
        {
            long long gi = (lane < 16) ? (base + lane)
                                       : ((long long)N_EDGES + base + lane - 16);
            si[lane] = (int)get_idx(ei, gi, is64);
        }

        // stage 16 e-rows transposed
        {
            int r = lane & 15, hh = lane >> 4;
            const float4* src = (const float4*)(e + (base + r) * HID + hh * 32);
            #pragma unroll
            for (int u = 0; u < 8; u++) {
                float4 v = src[u];
                int k = hh * 32 + u * 4;
                ew[(k + 0) * 16 + r] = v.x;
                ew[(k + 1) * 16 + r] = v.y;
                ew[(k + 2) * 16 + r] = v.z;
                ew[(k + 3) * 16 + r] = v.w;
            }
        }
        __syncwarp();

        ull acc[8][2];
        #pragma unroll
        for (int p = 0; p < 8; p++) { acc[p][0] = bias0; acc[p][1] = bias1; }

        #pragma unroll 8
        for (int k = 0; k < HID; k++) {
            float2 w2 = *(const float2*)&Ws[k * HID + 2 * lane];
            ull wa = dup2(w2.x);
            ull wb = dup2(w2.y);
            const ulonglong2* ep = (const ulonglong2*)&ew[k * 16];
            #pragma unroll
            for (int q = 0; q < 4; q++) {
                ulonglong2 ev = ep[q];
                fma2(acc[2 * q + 0][0], ev.x, wa);
                fma2(acc[2 * q + 0][1], ev.x, wb);
                fma2(acc[2 * q + 1][0], ev.y, wa);
                fma2(acc[2 * q + 1][1], ev.y, wb);
            }
        }
        __syncwarp();

        #pragma unroll
        for (int p = 0; p < 8; p++) {
            long long E0 = base + 2 * p, E1 = E0 + 1;
            int s0 = si[2 * p], s1 = si[2 * p + 1];
            int d0 = si[16 + 2 * p], d1 = si[16 + 2 * p + 1];

            float2 K0 = *(const float2*)&g_K[(long long)s0 * HID + 2 * lane];
            float2 Q0 = *(const float2*)&g_Q[(long long)d0 * HID + 2 * lane];
            float2 K1 = *(const float2*)&g_K[(long long)s1 * HID + 2 * lane];
            float2 Q1 = *(const float2*)&g_Q[(long long)d1 * HID + 2 * lane];

            float2 pA = up2(acc[p][0]);  // {pe_E0[c0], pe_E1[c0]}
            float2 pB = up2(acc[p][1]);  // {pe_E0[c1], pe_E1[c1]}
            float2 sc0, sc1;
            sc0.x = fmaf(K0.x * Q0.x, INV_SQRT8, pA.x);
            sc0.y = fmaf(K0.y * Q0.y, INV_SQRT8, pB.x);
            sc1.x = fmaf(K1.x * Q1.x, INV_SQRT8, pA.y);
            sc1.y = fmaf(K1.y * Q1.y, INV_SQRT8, pB.y);

            *(float2*)&e_out[E0 * HID + 2 * lane] = sc0;
            *(float2*)&e_out[E1 * HID + 2 * lane] = sc1;

            // per-head sums: head h = lane>>2 (8 cols = 4 lanes)
            float t0 = sc0.x + sc0.y;
            float t1 = sc1.x + sc1.y;
            t0 += __shfl_xor_sync(0xffffffffu, t0, 1);
            t1 += __shfl_xor_sync(0xffffffffu, t1, 1);
            t0 += __shfl_xor_sync(0xffffffffu, t0, 2);
            t1 += __shfl_xor_sync(0xffffffffu, t1, 2);
            float a0 = __expf(fminf(fmaxf(t0, -5.0f), 5.0f));
            float a1 = __expf(fminf(fmaxf(t1, -5.0f), 5.0f));
            float a0n = __shfl_xor_sync(0xffffffffu, a0, 4);  // head h^1
            float a1n = __shfl_xor_sync(0xffffffffu, a1, 4);
            if ((lane & 7) == 0) {
                red_add_v2(&g_z[(long long)s0 * 8 + (lane >> 2)], a0, a0n);
                red_add_v2(&g_z[(long long)s1 * 8 + (lane >> 2)], a1, a1n);
            }
            if (lane == 0) {
                red_add_f32(&g_cnt[s0], 1.0f);
                red_add_f32(&g_cnt[s1], 1.0f);
            }
        }
        __syncwarp();
    }
}

// ------------- final: h_out[n,h,:] = V[n,h,:]*S_h/(S_h/max(cnt,1)+1e-6) ----
__global__ void final_kernel(float* __restrict__ h_out) {
    int i = blockIdx.x * blockDim.x + threadIdx.x;   // float4 index
    if (i >= N_NODES * HID / 4) return;
    int n = i >> 4;
    int cg = i & 15;
    float S = g_z[n * 8 + (cg >> 1)];
    float cnt = g_cnt[n];
    float f = S / (S / fmaxf(cnt, 1.0f) + 1e-6f);
    float4 v = ((const float4*)g_V)[i];
    v.x *= f; v.y *= f; v.z *= f; v.w *= f;
    ((float4*)h_out)[i] = v;
}

// ---------------------------------------------------------------------------
extern "C" void kernel_launch(void* const* d_in, const int* in_sizes, int n_in,
                              void* d_out, int out_size) {
    const void* ei = d_in[0];
    const float* h = (const float*)d_in[1];
    const float* e = (const float*)d_in[2];
    const float* WQ = (const float*)d_in[3];
    const float* bQ = (const float*)d_in[4];
    const float* WK = (const float*)d_in[5];
    const float* bK = (const float*)d_in[6];
    const float* WV = (const float*)d_in[7];
    const float* bV = (const float*)d_in[8];
    const float* We = (const float*)d_in[9];
    const float* be = (const float*)d_in[10];

    float* out = (float*)d_out;
    float* h_out = out;                             // [50000*64]
    float* e_out = out + (long long)N_NODES * HID;  // [800000*64]

    static int attr_done = 0;
    const int PROJ_SMEM = (24576 + 16 * 1024) * 4;            // 163840 B
    const int EDGE_SMEM = (4096 + 8 * 1024) * 4 + 8 * 32 * 4; // 50176 B
    if (!attr_done) {
        cudaFuncSetAttribute(proj_fused_kernel,
                             cudaFuncAttributeMaxDynamicSharedMemorySize,
                             PROJ_SMEM);
        cudaFuncSetAttribute(edge_kernel,
                             cudaFuncAttributeMaxDynamicSharedMemorySize,
                             EDGE_SMEM);
        attr_done = 1;
    }

    zero_detect_kernel<<<391, 256>>>(ei);
    proj_fused_kernel<<<782, 512, PROJ_SMEM>>>(h, WQ, bQ, WK, bK, WV, bV);
    edge_kernel<<<444, 256, EDGE_SMEM>>>(ei, e, We, be, e_out);
    final_kernel<<<(N_NODES * HID / 4 + 255) / 256, 256>>>(h_out);
}